// round 4
// baseline (speedup 1.0000x reference)
#include <cuda_runtime.h>
#include <cstdint>
#include <math.h>

#define B_    4
#define H_    8
#define C_    64
#define T_    1024
#define SENC_ 1024

#define NT    256            // 8 warps
#define MQ    128            // queries per CTA (16 per warp)
#define NK    64             // keys per tile
#define NTILES 32

#define SCALE_LOG2 0.18033688011112042f   // 0.125 * log2(e)

// shared memory layout (bytes)
#define KP4   (72*4)                 // K tile row pitch: [ch=64][key 64], 72 floats
#define VP4   (68*4)                 // V tile row pitch: [ch=64][s 64],   68 floats
#define PP4   (68*4)                 // P/Q tile row pitch: [q=128][*],    68 floats
#define OQ4   (132*4)                // O staging pitch: [ch=64][q 128],   132 floats
#define VOFF  (64*KP4)               // 18432: V offset inside a stage
#define STAGE_B (64*KP4 + 64*VP4)    // 35840 per stage
#define P_OFF (3*STAGE_B)            // 107520
#define SMEM_BYTES (P_OFF + MQ*PP4)  // 142336

static __device__ __forceinline__ uint32_t smem_u32(const void* p) {
    uint32_t a;
    asm("{ .reg .u64 t; cvta.to.shared.u64 t, %1; cvt.u32.u64 %0, t; }" : "=r"(a) : "l"(p));
    return a;
}
static __device__ __forceinline__ uint32_t to_tf32(float x) {
    uint32_t u;
    asm("cvt.rna.tf32.f32 %0, %1;" : "=r"(u) : "f"(x));
    return u;
}
static __device__ __forceinline__ float fexp2(float x) {
    float r;
    asm("ex2.approx.ftz.f32 %0, %1;" : "=f"(r) : "f"(x));
    return r;
}
static __device__ __forceinline__ void sts32(uint32_t a, uint32_t v) {
    asm volatile("st.shared.b32 [%0], %1;" :: "r"(a), "r"(v) : "memory");
}
static __device__ __forceinline__ void sts64(uint32_t a, uint32_t v0, uint32_t v1) {
    asm volatile("st.shared.v2.b32 [%0], {%1,%2};" :: "r"(a), "r"(v0), "r"(v1) : "memory");
}
static __device__ __forceinline__ uint32_t lds32(uint32_t a) {
    uint32_t v;
    asm volatile("ld.shared.b32 %0, [%1];" : "=r"(v) : "r"(a));
    return v;
}
static __device__ __forceinline__ float lds32f(uint32_t a) {
    float v;
    asm volatile("ld.shared.b32 %0, [%1];" : "=f"(v) : "r"(a));
    return v;
}
static __device__ __forceinline__ uint32_t ldstf(uint32_t a) {   // lds + cvt to tf32
    return to_tf32(lds32f(a));
}
static __device__ __forceinline__ void cp16(uint32_t dst, const void* src) {
    asm volatile("cp.async.cg.shared.global [%0], [%1], 16;" :: "r"(dst), "l"(src) : "memory");
}
#define CP_COMMIT() asm volatile("cp.async.commit_group;" ::: "memory")
#define CP_WAIT2()  asm volatile("cp.async.wait_group 2;" ::: "memory")

// D += A*B : m16n8k8 tf32
static __device__ __forceinline__ void mma8(float* c, const uint32_t* a, uint32_t b0, uint32_t b1) {
    asm volatile("mma.sync.aligned.m16n8k8.row.col.f32.tf32.tf32.f32 "
        "{%0,%1,%2,%3}, {%4,%5,%6,%7}, {%8,%9}, {%0,%1,%2,%3};"
        : "+f"(c[0]), "+f"(c[1]), "+f"(c[2]), "+f"(c[3])
        : "r"(a[0]), "r"(a[1]), "r"(a[2]), "r"(a[3]), "r"(b0), "r"(b1));
}

__global__ void __launch_bounds__(NT, 1)
attn_mma8_kernel(const float* __restrict__ x,
                 const float* __restrict__ ekv,
                 float* __restrict__ out)
{
    extern __shared__ float smraw[];
    const uint32_t SB = smem_u32(smraw);

    const int tid = threadIdx.x;
    const int wid = tid >> 5;
    const int lid = tid & 31;
    const int lg  = lid >> 2;          // 0..7
    const int l4  = lid & 3;           // 0..3

    const int qt = blockIdx.x;
    const int bh = blockIdx.y;
    const int b  = bh >> 3;
    const int h  = bh & 7;
    const int q0 = qt * MQ;
    const int m0 = wid * 16;           // warp's query base within the CTA tile

    const float* qp  = x   + ((size_t)b * 3 * H_ * C_ + 0 * H_ * C_ + h * C_) * T_;
    const float* kp  = x   + ((size_t)b * 3 * H_ * C_ + 1 * H_ * C_ + h * C_) * T_;
    const float* vp  = x   + ((size_t)b * 3 * H_ * C_ + 2 * H_ * C_ + h * C_) * T_;
    const float* ekp = ekv + ((size_t)b * 2 * H_ * C_ + 0 * H_ * C_ + h * C_) * SENC_;
    const float* evp = ekv + ((size_t)b * 2 * H_ * C_ + 1 * H_ * C_ + h * C_) * SENC_;
    float* op = out + ((size_t)b * H_ * C_ + h * C_) * T_;

    // ---- prefetch K/V tiles 0,1,2 via cp.async (raw fp32) ----
    #pragma unroll
    for (int pf = 0; pf < 3; pf++) {
        const float* ks = ekp; const float* vs = evp;
        int soff = pf * NK, str = SENC_;
        uint32_t st = SB + (uint32_t)pf * STAGE_B;
        #pragma unroll
        for (int it = 0; it < 4; it++) {
            int i  = tid + it * NT;            // 1024 16B-chunks each for K and V
            int ch = i >> 4, s4 = i & 15;
            const float* src = ks + (size_t)ch * str + soff + 4 * s4;
            const float* srv = vs + (size_t)ch * str + soff + 4 * s4;
            cp16(st + (uint32_t)ch * KP4 + (uint32_t)s4 * 16u, src);
            cp16(st + VOFF + (uint32_t)ch * VP4 + (uint32_t)s4 * 16u, srv);
        }
        CP_COMMIT();
    }

    // ---- stage Q [q=128][ch=64] (tf32) into P area ----
    #pragma unroll
    for (int it = 0; it < 8; it++) {
        int j  = tid + it * NT;                // 2048 float4s
        int ch = j >> 5;
        int q4 = (j & 31) << 2;
        float4 v = *(const float4*)(qp + (size_t)ch * T_ + q0 + q4);
        uint32_t base = SB + P_OFF + (uint32_t)ch * 4u;
        sts32(base + (uint32_t)(q4 + 0) * PP4, to_tf32(v.x));
        sts32(base + (uint32_t)(q4 + 1) * PP4, to_tf32(v.y));
        sts32(base + (uint32_t)(q4 + 2) * PP4, to_tf32(v.z));
        sts32(base + (uint32_t)(q4 + 3) * PP4, to_tf32(v.w));
    }
    __syncthreads();

    // ---- resident Q fragments: 16 queries/warp ----
    uint32_t qa[8][4];
    {
        uint32_t qb = SB + P_OFF + (uint32_t)(m0 + lg) * PP4 + (uint32_t)l4 * 4u;
        #pragma unroll
        for (int kc = 0; kc < 8; kc++) {
            uint32_t a = qb + (uint32_t)kc * 32u;
            qa[kc][0] = lds32(a);
            qa[kc][1] = lds32(a + 8u * PP4);
            qa[kc][2] = lds32(a + 16u);
            qa[kc][3] = lds32(a + 8u * PP4 + 16u);
        }
    }

    float oc[8][4];
    float lsum[2] = {0.f, 0.f};
    #pragma unroll
    for (int nc = 0; nc < 8; nc++)
        #pragma unroll
        for (int e = 0; e < 4; e++) oc[nc][e] = 0.f;

    const uint32_t pst = SB + P_OFF + (uint32_t)(m0 + lg) * PP4 + (uint32_t)(2 * l4) * 4u;
    const uint32_t pld = SB + P_OFF + (uint32_t)(m0 + lg) * PP4 + (uint32_t)l4 * 4u;

    int stg = 0;
    #pragma unroll 1
    for (int kt = 0; kt < NTILES; kt++) {
        CP_WAIT2();
        __syncthreads();
        const uint32_t st  = SB + (uint32_t)stg * STAGE_B;
        const uint32_t kfb = st + (uint32_t)l4 * KP4 + (uint32_t)lg * 4u;
        const uint32_t vfb = st + VOFF + (uint32_t)lg * VP4 + (uint32_t)l4 * 4u;

        // ---- S = Q K^T ----
        float sc[8][4];
        #pragma unroll
        for (int nc = 0; nc < 8; nc++)
            #pragma unroll
            for (int e = 0; e < 4; e++) sc[nc][e] = 0.f;

        #pragma unroll
        for (int kc = 0; kc < 8; kc++) {
            #pragma unroll
            for (int nc = 0; nc < 8; nc++) {
                uint32_t a = kfb + (uint32_t)kc * 8u * KP4 + (uint32_t)nc * 32u;
                uint32_t b0 = ldstf(a);
                uint32_t b1 = ldstf(a + 4u * KP4);
                mma8(sc[nc], qa[kc], b0, b1);
            }
        }

        // ---- softmax (no running max; logits O(1)) → P (tf32) to smem ----
        #pragma unroll
        for (int nc = 0; nc < 8; nc++) {
            float p0 = fexp2(sc[nc][0] * SCALE_LOG2);
            float p1 = fexp2(sc[nc][1] * SCALE_LOG2);
            float p2 = fexp2(sc[nc][2] * SCALE_LOG2);
            float p3 = fexp2(sc[nc][3] * SCALE_LOG2);
            lsum[0] += p0 + p1;
            lsum[1] += p2 + p3;
            uint32_t a = pst + (uint32_t)nc * 32u;
            sts64(a,            to_tf32(p0), to_tf32(p1));
            sts64(a + 8u * PP4, to_tf32(p2), to_tf32(p3));
        }
        __syncwarp();   // P rows are warp-private

        // ---- O += P V^T ----
        #pragma unroll
        for (int kc = 0; kc < 8; kc++) {
            uint32_t pa[4];
            {
                uint32_t a = pld + (uint32_t)kc * 32u;
                pa[0] = lds32(a);
                pa[1] = lds32(a + 8u * PP4);
                pa[2] = lds32(a + 16u);
                pa[3] = lds32(a + 8u * PP4 + 16u);
            }
            #pragma unroll
            for (int nc = 0; nc < 8; nc++) {
                uint32_t a = vfb + (uint32_t)nc * 8u * VP4 + (uint32_t)kc * 32u;
                uint32_t b0 = ldstf(a);
                uint32_t b1 = ldstf(a + 16u);
                mma8(oc[nc], pa, b0, b1);
            }
        }

        __syncthreads();   // all warps done with this stage

        // ---- prefetch tile kt+3 into the stage just freed ----
        int nt = kt + 3;
        if (nt < NTILES) {
            const float* ks; const float* vs; int soff, str;
            if (nt < 16) { ks = ekp; vs = evp; soff = nt * NK;         str = SENC_; }
            else         { ks = kp;  vs = vp;  soff = nt * NK - SENC_; str = T_;    }
            #pragma unroll
            for (int it = 0; it < 4; it++) {
                int i  = tid + it * NT;
                int ch = i >> 4, s4 = i & 15;
                cp16(st + (uint32_t)ch * KP4 + (uint32_t)s4 * 16u,
                     ks + (size_t)ch * str + soff + 4 * s4);
                cp16(st + VOFF + (uint32_t)ch * VP4 + (uint32_t)s4 * 16u,
                     vs + (size_t)ch * str + soff + 4 * s4);
            }
        }
        CP_COMMIT();       // commit even when empty (keeps wait_group bookkeeping exact)

        stg = (stg == 2) ? 0 : stg + 1;
    }

    // ---- epilogue: reduce sums over quads, normalize, transpose via smem ----
    {
        float v0 = lsum[0], v1 = lsum[1];
        v0 += __shfl_xor_sync(0xffffffffu, v0, 1);
        v0 += __shfl_xor_sync(0xffffffffu, v0, 2);
        v1 += __shfl_xor_sync(0xffffffffu, v1, 1);
        v1 += __shfl_xor_sync(0xffffffffu, v1, 2);
        lsum[0] = 1.0f / v0;
        lsum[1] = 1.0f / v1;
    }

    __syncthreads();       // everyone finished their last PV reads of P area
    // O staging as [ch=64][q=128], pitch 132 floats (conflict-free sts32 / lds128)
    #pragma unroll
    for (int nc = 0; nc < 8; nc++) {
        int ch = 8 * nc + 2 * l4;
        uint32_t a0 = SB + P_OFF + (uint32_t)ch * OQ4 + (uint32_t)(m0 + lg) * 4u;
        sts32(a0,                  __float_as_uint(oc[nc][0] * lsum[0]));
        sts32(a0 + OQ4,            __float_as_uint(oc[nc][1] * lsum[0]));
        sts32(a0 + 32u,            __float_as_uint(oc[nc][2] * lsum[1]));
        sts32(a0 + OQ4 + 32u,      __float_as_uint(oc[nc][3] * lsum[1]));
    }
    __syncthreads();

    // coalesced store out[ch][t]
    #pragma unroll
    for (int it = 0; it < 8; it++) {
        int j  = tid + it * NT;            // 2048 float4s
        int ch = j >> 5;
        int q4 = (j & 31) << 2;
        uint32_t a = SB + P_OFF + (uint32_t)ch * OQ4 + (uint32_t)q4 * 4u;
        float4 v;
        asm volatile("ld.shared.v4.b32 {%0,%1,%2,%3}, [%4];"
                     : "=f"(v.x), "=f"(v.y), "=f"(v.z), "=f"(v.w) : "r"(a));
        *(float4*)(op + (size_t)ch * T_ + q0 + q4) = v;
    }
}

extern "C" void kernel_launch(void* const* d_in, const int* in_sizes, int n_in,
                              void* d_out, int out_size)
{
    const float* x   = (const float*)d_in[0];   // (4, 1536, 1024)
    const float* ekv = (const float*)d_in[1];   // (4, 1024, 1024)
    float* out = (float*)d_out;                 // (4, 512, 1024)

    cudaFuncSetAttribute(attn_mma8_kernel, cudaFuncAttributeMaxDynamicSharedMemorySize, SMEM_BYTES);
    dim3 grid(T_ / MQ, B_ * H_);                // (8, 32) = 256 CTAs
    attn_mma8_kernel<<<grid, NT, SMEM_BYTES>>>(x, ekv, out);
}

// round 5
// speedup vs baseline: 1.0965x; 1.0965x over previous
#include <cuda_runtime.h>
#include <cstdint>
#include <math.h>

#define B_    4
#define H_    8
#define C_    64
#define T_    1024
#define SENC_ 1024

#define NT    256            // 8 warps: wq = wid&3 (32 queries), wk = wid>>2 (32-key half)
#define MQ    128            // queries per CTA
#define NK    64             // keys per tile
#define NTILES 32

#define SCALE_LOG2 0.18033688011112042f   // 0.125 * log2(e)

// shared memory layout (bytes)
#define KP4   (72*4)                 // K tile row pitch: [ch=64][key 64]
#define VP4   (68*4)                 // V tile row pitch: [ch=64][s 64]
#define PP4   (68*4)                 // P/Q tile row pitch: [q=128][*]
#define OQ4   (132*4)                // O staging pitch: [ch=64][q 128]
#define VOFF  (64*KP4)               // 18432
#define STAGE_B (64*KP4 + 64*VP4)    // 35840
#define NSTG  4
#define P_OFF (NSTG*STAGE_B)         // 143360
#define LS_OFF (P_OFF + 64*OQ4)      // Ls arrays live after O staging area
#define SMEM_BYTES (P_OFF + MQ*PP4)  // 178176 (P area = 34816 >= 33792 + 1024)

static __device__ __forceinline__ uint32_t smem_u32(const void* p) {
    uint32_t a;
    asm("{ .reg .u64 t; cvta.to.shared.u64 t, %1; cvt.u32.u64 %0, t; }" : "=r"(a) : "l"(p));
    return a;
}
static __device__ __forceinline__ uint32_t to_tf32(float x) {
    uint32_t u;
    asm("cvt.rna.tf32.f32 %0, %1;" : "=r"(u) : "f"(x));
    return u;
}
static __device__ __forceinline__ float fexp2(float x) {
    float r;
    asm("ex2.approx.ftz.f32 %0, %1;" : "=f"(r) : "f"(x));
    return r;
}
static __device__ __forceinline__ void sts32(uint32_t a, uint32_t v) {
    asm volatile("st.shared.b32 [%0], %1;" :: "r"(a), "r"(v) : "memory");
}
static __device__ __forceinline__ void sts64(uint32_t a, uint32_t v0, uint32_t v1) {
    asm volatile("st.shared.v2.b32 [%0], {%1,%2};" :: "r"(a), "r"(v0), "r"(v1) : "memory");
}
static __device__ __forceinline__ uint32_t lds32(uint32_t a) {
    uint32_t v;
    asm volatile("ld.shared.b32 %0, [%1];" : "=r"(v) : "r"(a));
    return v;
}
static __device__ __forceinline__ float lds32f(uint32_t a) {
    float v;
    asm volatile("ld.shared.b32 %0, [%1];" : "=f"(v) : "r"(a));
    return v;
}
static __device__ __forceinline__ uint32_t ldstf(uint32_t a) {   // lds + cvt to tf32
    return to_tf32(lds32f(a));
}
static __device__ __forceinline__ void cp16(uint32_t dst, const void* src) {
    asm volatile("cp.async.cg.shared.global [%0], [%1], 16;" :: "r"(dst), "l"(src) : "memory");
}
#define CP_COMMIT() asm volatile("cp.async.commit_group;" ::: "memory")
#define CP_WAIT2()  asm volatile("cp.async.wait_group 2;" ::: "memory")

// D += A*B : m16n8k8 tf32
static __device__ __forceinline__ void mma8(float* c, const uint32_t* a, uint32_t b0, uint32_t b1) {
    asm volatile("mma.sync.aligned.m16n8k8.row.col.f32.tf32.tf32.f32 "
        "{%0,%1,%2,%3}, {%4,%5,%6,%7}, {%8,%9}, {%0,%1,%2,%3};"
        : "+f"(c[0]), "+f"(c[1]), "+f"(c[2]), "+f"(c[3])
        : "r"(a[0]), "r"(a[1]), "r"(a[2]), "r"(a[3]), "r"(b0), "r"(b1));
}

__global__ void __launch_bounds__(NT, 1)
attn_ks_kernel(const float* __restrict__ x,
               const float* __restrict__ ekv,
               float* __restrict__ out)
{
    extern __shared__ float smraw[];
    const uint32_t SB = smem_u32(smraw);

    const int tid = threadIdx.x;
    const int wid = tid >> 5;
    const int lid = tid & 31;
    const int lg  = lid >> 2;          // 0..7
    const int l4  = lid & 3;           // 0..3
    const int wq  = wid & 3;           // query group (32 q)
    const int wk  = wid >> 2;          // key half (32 keys of the 64-key tile)
    const int m0  = wq * 32;
    const int kb  = wk * 32;           // key base within tile

    const int qt = blockIdx.x;
    const int bh = blockIdx.y;
    const int b  = bh >> 3;
    const int h  = bh & 7;
    const int q0 = qt * MQ;

    const float* qp  = x   + ((size_t)b * 3 * H_ * C_ + 0 * H_ * C_ + h * C_) * T_;
    const float* kp  = x   + ((size_t)b * 3 * H_ * C_ + 1 * H_ * C_ + h * C_) * T_;
    const float* vp  = x   + ((size_t)b * 3 * H_ * C_ + 2 * H_ * C_ + h * C_) * T_;
    const float* ekp = ekv + ((size_t)b * 2 * H_ * C_ + 0 * H_ * C_ + h * C_) * SENC_;
    const float* evp = ekv + ((size_t)b * 2 * H_ * C_ + 1 * H_ * C_ + h * C_) * SENC_;
    float* op = out + ((size_t)b * H_ * C_ + h * C_) * T_;

    // ---- prologue: prefetch tiles 0..2 (raw fp32) ----
    #pragma unroll
    for (int pf = 0; pf < 3; pf++) {
        int soff = pf * NK;
        uint32_t st = SB + (uint32_t)pf * STAGE_B;
        #pragma unroll
        for (int it = 0; it < 4; it++) {
            int i  = tid + it * NT;          // 1024 chunks each for K and V
            int ch = i >> 4, s4 = i & 15;
            cp16(st + (uint32_t)ch * KP4 + (uint32_t)s4 * 16u,
                 ekp + (size_t)ch * SENC_ + soff + 4 * s4);
            cp16(st + VOFF + (uint32_t)ch * VP4 + (uint32_t)s4 * 16u,
                 evp + (size_t)ch * SENC_ + soff + 4 * s4);
        }
        CP_COMMIT();
    }

    // ---- stage Q [q=128][ch=64] (tf32) into P area ----
    #pragma unroll
    for (int it = 0; it < 8; it++) {
        int j  = tid + it * NT;              // 2048 float4s
        int ch = j >> 5;
        int q4 = (j & 31) << 2;
        float4 v = *(const float4*)(qp + (size_t)ch * T_ + q0 + q4);
        uint32_t base = SB + P_OFF + (uint32_t)ch * 4u;
        sts32(base + (uint32_t)(q4 + 0) * PP4, to_tf32(v.x));
        sts32(base + (uint32_t)(q4 + 1) * PP4, to_tf32(v.y));
        sts32(base + (uint32_t)(q4 + 2) * PP4, to_tf32(v.z));
        sts32(base + (uint32_t)(q4 + 3) * PP4, to_tf32(v.w));
    }
    __syncthreads();

    // ---- resident Q fragments: 32 queries/warp (mb=2) ----
    uint32_t qa[2][8][4];
    {
        uint32_t qb = SB + P_OFF + (uint32_t)(m0 + lg) * PP4 + (uint32_t)l4 * 4u;
        #pragma unroll
        for (int mb = 0; mb < 2; mb++)
            #pragma unroll
            for (int kc = 0; kc < 8; kc++) {
                uint32_t a = qb + (uint32_t)mb * 16u * PP4 + (uint32_t)kc * 32u;
                qa[mb][kc][0] = lds32(a);
                qa[mb][kc][1] = lds32(a + 8u * PP4);
                qa[mb][kc][2] = lds32(a + 16u);
                qa[mb][kc][3] = lds32(a + 8u * PP4 + 16u);
            }
    }

    float oc[2][8][4];                 // partial O over this warp's key half
    float lsum[2][2] = {{0.f,0.f},{0.f,0.f}};
    #pragma unroll
    for (int mb = 0; mb < 2; mb++)
        #pragma unroll
        for (int nc = 0; nc < 8; nc++)
            #pragma unroll
            for (int e = 0; e < 4; e++) oc[mb][nc][e] = 0.f;

    const uint32_t pst = SB + P_OFF + (uint32_t)(m0 + lg) * PP4 + (uint32_t)(kb + 2 * l4) * 4u;
    const uint32_t pld = SB + P_OFF + (uint32_t)(m0 + lg) * PP4 + (uint32_t)(kb + l4) * 4u;

    #pragma unroll 1
    for (int kt = 0; kt < NTILES; kt++) {
        CP_WAIT2();
        __syncthreads();               // tile kt visible; stage (kt+3)&3 free (computed at kt-1)

        // prefetch tile kt+3 into stage (kt+3)&3
        {
            int nt = kt + 3;
            if (nt < NTILES) {
                const float* ks; const float* vs; int soff, str;
                if (nt < 16) { ks = ekp; vs = evp; soff = nt * NK;         str = SENC_; }
                else         { ks = kp;  vs = vp;  soff = nt * NK - SENC_; str = T_;    }
                uint32_t st = SB + (uint32_t)(nt & 3) * STAGE_B;
                #pragma unroll
                for (int it = 0; it < 4; it++) {
                    int i  = tid + it * NT;
                    int ch = i >> 4, s4 = i & 15;
                    cp16(st + (uint32_t)ch * KP4 + (uint32_t)s4 * 16u,
                         ks + (size_t)ch * str + soff + 4 * s4);
                    cp16(st + VOFF + (uint32_t)ch * VP4 + (uint32_t)s4 * 16u,
                         vs + (size_t)ch * str + soff + 4 * s4);
                }
            }
            CP_COMMIT();
        }

        const uint32_t st  = SB + (uint32_t)(kt & 3) * STAGE_B;
        const uint32_t kfb = st + (uint32_t)l4 * KP4 + (uint32_t)(kb + lg) * 4u;
        const uint32_t vfb = st + VOFF + (uint32_t)lg * VP4 + (uint32_t)(kb + l4) * 4u;

        // ---- S = Q K^T  (this warp's 32 keys) ----
        float sc[2][4][4];
        #pragma unroll
        for (int mb = 0; mb < 2; mb++)
            #pragma unroll
            for (int nc = 0; nc < 4; nc++)
                #pragma unroll
                for (int e = 0; e < 4; e++) sc[mb][nc][e] = 0.f;

        #pragma unroll
        for (int kc = 0; kc < 8; kc++) {
            #pragma unroll
            for (int nc = 0; nc < 4; nc++) {
                uint32_t a = kfb + (uint32_t)kc * 8u * KP4 + (uint32_t)nc * 32u;
                uint32_t b0 = ldstf(a);
                uint32_t b1 = ldstf(a + 4u * KP4);
                mma8(sc[0][nc], qa[0][kc], b0, b1);
                mma8(sc[1][nc], qa[1][kc], b0, b1);
            }
        }

        // ---- softmax (no running max; logits O(1)) → P (tf32) to smem ----
        #pragma unroll
        for (int mb = 0; mb < 2; mb++) {
            #pragma unroll
            for (int nc = 0; nc < 4; nc++) {
                float p0 = fexp2(sc[mb][nc][0] * SCALE_LOG2);
                float p1 = fexp2(sc[mb][nc][1] * SCALE_LOG2);
                float p2 = fexp2(sc[mb][nc][2] * SCALE_LOG2);
                float p3 = fexp2(sc[mb][nc][3] * SCALE_LOG2);
                lsum[mb][0] += p0 + p1;
                lsum[mb][1] += p2 + p3;
                uint32_t a = pst + (uint32_t)mb * 16u * PP4 + (uint32_t)nc * 32u;
                sts64(a,            to_tf32(p0), to_tf32(p1));
                sts64(a + 8u * PP4, to_tf32(p2), to_tf32(p3));
            }
        }
        __syncwarp();   // each warp reads back only its own P columns

        // ---- O += P V^T  (this warp's 32 keys, all 64 channels) ----
        #pragma unroll
        for (int kc = 0; kc < 4; kc++) {
            uint32_t pa[2][4];
            #pragma unroll
            for (int mb = 0; mb < 2; mb++) {
                uint32_t a = pld + (uint32_t)mb * 16u * PP4 + (uint32_t)kc * 32u;
                pa[mb][0] = lds32(a);
                pa[mb][1] = lds32(a + 8u * PP4);
                pa[mb][2] = lds32(a + 16u);
                pa[mb][3] = lds32(a + 8u * PP4 + 16u);
            }
            #pragma unroll
            for (int nc = 0; nc < 8; nc++) {
                uint32_t a = vfb + (uint32_t)nc * 8u * VP4 + (uint32_t)kc * 32u;
                uint32_t b0 = ldstf(a);
                uint32_t b1 = ldstf(a + 16u);
                mma8(oc[0][nc], pa[0], b0, b1);
                mma8(oc[1][nc], pa[1], b0, b1);
            }
        }
    }

    // ---- epilogue: merge the two key-half partials, normalize, store ----
    // quad-reduce row sums (over n within this warp's half)
    #pragma unroll
    for (int mb = 0; mb < 2; mb++)
        #pragma unroll
        for (int hh = 0; hh < 2; hh++) {
            float v = lsum[mb][hh];
            v += __shfl_xor_sync(0xffffffffu, v, 1);
            v += __shfl_xor_sync(0xffffffffu, v, 2);
            lsum[mb][hh] = v;
        }

    __syncthreads();   // all tile compute done; P area reusable as O staging + Ls
    const uint32_t OST = SB + P_OFF;
    const uint32_t LSA = SB + LS_OFF;
    const uint32_t LSB = LSA + 512u;

    if (wk == 0) {
        // write raw partial O and LsA
        #pragma unroll
        for (int mb = 0; mb < 2; mb++) {
            int qrow = m0 + mb * 16 + lg;
            if (l4 == 0) {
                sts32(LSA + (uint32_t)qrow * 4u,       __float_as_uint(lsum[mb][0]));
                sts32(LSA + (uint32_t)(qrow + 8) * 4u, __float_as_uint(lsum[mb][1]));
            }
            #pragma unroll
            for (int nc = 0; nc < 8; nc++) {
                int ch = 8 * nc + 2 * l4;
                uint32_t a0 = OST + (uint32_t)ch * OQ4 + (uint32_t)qrow * 4u;
                sts32(a0,             __float_as_uint(oc[mb][nc][0]));
                sts32(a0 + OQ4,       __float_as_uint(oc[mb][nc][1]));
                sts32(a0 + 32u,       __float_as_uint(oc[mb][nc][2]));
                sts32(a0 + OQ4 + 32u, __float_as_uint(oc[mb][nc][3]));
            }
        }
    } else {
        #pragma unroll
        for (int mb = 0; mb < 2; mb++) {
            int qrow = m0 + mb * 16 + lg;
            if (l4 == 0) {
                sts32(LSB + (uint32_t)qrow * 4u,       __float_as_uint(lsum[mb][0]));
                sts32(LSB + (uint32_t)(qrow + 8) * 4u, __float_as_uint(lsum[mb][1]));
            }
        }
    }
    __syncthreads();

    if (wk == 1) {
        #pragma unroll
        for (int mb = 0; mb < 2; mb++) {
            int qrow = m0 + mb * 16 + lg;
            float la0 = lds32f(LSA + (uint32_t)qrow * 4u) + lds32f(LSB + (uint32_t)qrow * 4u);
            float la1 = lds32f(LSA + (uint32_t)(qrow + 8) * 4u) + lds32f(LSB + (uint32_t)(qrow + 8) * 4u);
            float inv0 = 1.0f / la0;
            float inv1 = 1.0f / la1;
            #pragma unroll
            for (int nc = 0; nc < 8; nc++) {
                int ch = 8 * nc + 2 * l4;
                uint32_t a0 = OST + (uint32_t)ch * OQ4 + (uint32_t)qrow * 4u;
                float t0 = lds32f(a0)             + oc[mb][nc][0];
                float t1 = lds32f(a0 + OQ4)       + oc[mb][nc][1];
                float t2 = lds32f(a0 + 32u)       + oc[mb][nc][2];
                float t3 = lds32f(a0 + OQ4 + 32u) + oc[mb][nc][3];
                sts32(a0,             __float_as_uint(t0 * inv0));
                sts32(a0 + OQ4,       __float_as_uint(t1 * inv0));
                sts32(a0 + 32u,       __float_as_uint(t2 * inv1));
                sts32(a0 + OQ4 + 32u, __float_as_uint(t3 * inv1));
            }
        }
    }
    __syncthreads();

    // coalesced store out[ch][t]
    #pragma unroll
    for (int it = 0; it < 8; it++) {
        int j  = tid + it * NT;            // 2048 float4s
        int ch = j >> 5;
        int q4 = (j & 31) << 2;
        uint32_t a = OST + (uint32_t)ch * OQ4 + (uint32_t)q4 * 4u;
        float4 v;
        asm volatile("ld.shared.v4.b32 {%0,%1,%2,%3}, [%4];"
                     : "=f"(v.x), "=f"(v.y), "=f"(v.z), "=f"(v.w) : "r"(a));
        *(float4*)(op + (size_t)ch * T_ + q0 + q4) = v;
    }
}

extern "C" void kernel_launch(void* const* d_in, const int* in_sizes, int n_in,
                              void* d_out, int out_size)
{
    const float* x   = (const float*)d_in[0];   // (4, 1536, 1024)
    const float* ekv = (const float*)d_in[1];   // (4, 1024, 1024)
    float* out = (float*)d_out;                 // (4, 512, 1024)

    cudaFuncSetAttribute(attn_ks_kernel, cudaFuncAttributeMaxDynamicSharedMemorySize, SMEM_BYTES);
    dim3 grid(T_ / MQ, B_ * H_);                // (8, 32) = 256 CTAs
    attn_ks_kernel<<<grid, NT, SMEM_BYTES>>>(x, ekv, out);
}

// round 6
// speedup vs baseline: 1.9849x; 1.8102x over previous
#include <cuda_runtime.h>
#include <cstdint>

#define B_    4
#define H_    8
#define C_    64
#define T_    1024
#define SENC_ 1024

#define NT    128            // 4 warps, each owns 32 queries, full 64-key tiles
#define MQ    128
#define NK    64
#define NTILES 32

#define SCALE_LOG2 0.18033688011112042f   // 0.125 * log2(e), folded into Q

// ---- smem map (bytes from dynamic base) ----
// fp32 staging ring (2 stages), each stage = K[64][68] + V[64][68] fp32
#define F32P   68u                  // fp32 buf pitch (words)
#define F32VO  17408u               // V area offset inside a stage
#define STAGEB 34816u               // bytes per stage
#define K2OFF  69632u               // fp16 K2 [32 chpair][64 key], pitch 72 words
#define V2OFF  78848u               // fp16 V2 [32 keypair][64 ch], pitch 72 words
#define P2OFF  88064u               // P2/Q2 [128 q][32 +4 pad], pitch 36 words
#define SMEM_BYTES 106496u

static __device__ __forceinline__ uint32_t smem_u32(const void* p) {
    uint32_t a;
    asm("{ .reg .u64 t; cvta.to.shared.u64 t, %1; cvt.u32.u64 %0, t; }" : "=r"(a) : "l"(p));
    return a;
}
static __device__ __forceinline__ float fexp2(float x) {
    float r; asm("ex2.approx.ftz.f32 %0, %1;" : "=f"(r) : "f"(x)); return r;
}
static __device__ __forceinline__ uint32_t cvt2h(float hi, float lo) {   // half2{lo,hi}
    uint32_t d; asm("cvt.rn.f16x2.f32 %0, %1, %2;" : "=r"(d) : "f"(hi), "f"(lo)); return d;
}
static __device__ __forceinline__ void sts32(uint32_t a, uint32_t v) {
    asm volatile("st.shared.b32 [%0], %1;" :: "r"(a), "r"(v) : "memory");
}
static __device__ __forceinline__ void sts128(uint32_t a, uint32_t v0, uint32_t v1, uint32_t v2, uint32_t v3) {
    asm volatile("st.shared.v4.b32 [%0], {%1,%2,%3,%4};" :: "r"(a), "r"(v0), "r"(v1), "r"(v2), "r"(v3) : "memory");
}
static __device__ __forceinline__ uint32_t lds32(uint32_t a) {
    uint32_t v; asm volatile("ld.shared.b32 %0, [%1];" : "=r"(v) : "r"(a)); return v;
}
static __device__ __forceinline__ float lds32f(uint32_t a) {
    float v; asm volatile("ld.shared.b32 %0, [%1];" : "=f"(v) : "r"(a)); return v;
}
static __device__ __forceinline__ float2 lds64f(uint32_t a) {
    float2 v; asm volatile("ld.shared.v2.b32 {%0,%1}, [%2];" : "=f"(v.x), "=f"(v.y) : "r"(a)); return v;
}
static __device__ __forceinline__ float4 lds128f(uint32_t a) {
    float4 v;
    asm volatile("ld.shared.v4.b32 {%0,%1,%2,%3}, [%4];"
                 : "=f"(v.x), "=f"(v.y), "=f"(v.z), "=f"(v.w) : "r"(a));
    return v;
}
static __device__ __forceinline__ void cp16(uint32_t dst, const void* src) {
    asm volatile("cp.async.cg.shared.global [%0], [%1], 16;" :: "r"(dst), "l"(src) : "memory");
}
#define CP_COMMIT() asm volatile("cp.async.commit_group;" ::: "memory")
#define CP_WAIT1()  asm volatile("cp.async.wait_group 1;" ::: "memory")

// D += A*B : m16n8k16 fp16 in, fp32 accum
static __device__ __forceinline__ void mma16(float* c, const uint32_t* a, uint32_t b0, uint32_t b1) {
    asm volatile("mma.sync.aligned.m16n8k16.row.col.f32.f16.f16.f32 "
        "{%0,%1,%2,%3}, {%4,%5,%6,%7}, {%8,%9}, {%0,%1,%2,%3};"
        : "+f"(c[0]), "+f"(c[1]), "+f"(c[2]), "+f"(c[3])
        : "r"(a[0]), "r"(a[1]), "r"(a[2]), "r"(a[3]), "r"(b0), "r"(b1));
}

__global__ void __launch_bounds__(NT, 2)
attn_fp16_kernel(const float* __restrict__ x,
                 const float* __restrict__ ekv,
                 float* __restrict__ out)
{
    extern __shared__ float smraw[];
    const uint32_t SB = smem_u32(smraw);

    const int tid = threadIdx.x;
    const int wid = tid >> 5;
    const int lid = tid & 31;
    const int lg  = lid >> 2;          // 0..7
    const int l4  = lid & 3;           // 0..3
    const int m0  = wid * 32;          // warp query base

    const int qt = blockIdx.x;
    const int bh = blockIdx.y;
    const int b  = bh >> 3;
    const int h  = bh & 7;
    const int q0 = qt * MQ;

    const float* qp  = x   + ((size_t)b * 3 * H_ * C_ + 0 * H_ * C_ + h * C_) * T_;
    const float* kp  = x   + ((size_t)b * 3 * H_ * C_ + 1 * H_ * C_ + h * C_) * T_;
    const float* vp  = x   + ((size_t)b * 3 * H_ * C_ + 2 * H_ * C_ + h * C_) * T_;
    const float* ekp = ekv + ((size_t)b * 2 * H_ * C_ + 0 * H_ * C_ + h * C_) * SENC_;
    const float* evp = ekv + ((size_t)b * 2 * H_ * C_ + 1 * H_ * C_ + h * C_) * SENC_;
    float* op = out + ((size_t)b * H_ * C_ + h * C_) * T_;

    // ---- prologue: cp.async Q (fp32) into stage0 [K-area: q<64 | V-area: q>=64] ----
    {
        int ch = tid >> 5;             // will add it*4
        int q4 = tid & 31;
        #pragma unroll
        for (int it = 0; it < 16; it++) {
            int c  = ch + it * 4;      // 0..63
            uint32_t dst = (q4 < 16)
                ? SB + ((uint32_t)c * F32P + 4u * q4) * 4u
                : SB + F32VO + ((uint32_t)c * F32P + 4u * (q4 - 16)) * 4u;
            cp16(dst, qp + (size_t)c * T_ + q0 + 4 * q4);
        }
        CP_COMMIT();
    }
    // ---- cp.async K/V tile 0 -> stage1 ----
    {
        uint32_t st = SB + STAGEB;
        int k4 = tid & 15;
        #pragma unroll
        for (int it = 0; it < 16; it++) {
            int idx = tid + it * NT;
            int m   = idx >> 10;                 // 0:K 1:V
            int ch  = (idx & 1023) >> 4;
            const float* src = (m ? evp : ekp) + (size_t)ch * SENC_ + 4 * k4;
            cp16(st + (uint32_t)m * F32VO + ((uint32_t)ch * F32P + 4u * k4) * 4u, src);
        }
        CP_COMMIT();
    }

    CP_WAIT1();            // Q landed
    __syncthreads();

    // ---- convert Q: fp32 stage0 -> Q2 (fp16, scaled), [q][chpair] pitch 36 ----
    {
        int q = tid;                   // 0..127
        uint32_t area = (q < 64) ? SB : SB + F32VO;
        uint32_t col  = (uint32_t)(q & 63);
        #pragma unroll
        for (int cg = 0; cg < 8; cg++) {
            float f[8];
            #pragma unroll
            for (int j = 0; j < 8; j++)
                f[j] = lds32f(area + (((uint32_t)(8 * cg + j)) * F32P + col) * 4u) * SCALE_LOG2;
            uint32_t h0 = cvt2h(f[1], f[0]);
            uint32_t h1 = cvt2h(f[3], f[2]);
            uint32_t h2 = cvt2h(f[5], f[4]);
            uint32_t h3 = cvt2h(f[7], f[6]);
            sts128(SB + P2OFF + ((uint32_t)q * 36u + 4u * cg) * 4u, h0, h1, h2, h3);
        }
    }
    __syncthreads();

    // ---- cp.async K/V tile 1 -> stage0 (Q fp32 is dead now) ----
    {
        int k4 = tid & 15;
        #pragma unroll
        for (int it = 0; it < 16; it++) {
            int idx = tid + it * NT;
            int m   = idx >> 10;
            int ch  = (idx & 1023) >> 4;
            const float* src = (m ? evp : ekp) + (size_t)ch * SENC_ + NK + 4 * k4;
            cp16(SB + (uint32_t)m * F32VO + ((uint32_t)ch * F32P + 4u * k4) * 4u, src);
        }
        CP_COMMIT();
    }

    // ---- resident Q fragments (fp16): qa[mb][kc][4] ----
    uint32_t qa[2][4][4];
    #pragma unroll
    for (int mb = 0; mb < 2; mb++) {
        uint32_t rb = SB + P2OFF + ((uint32_t)(m0 + 16 * mb + lg) * 36u + (uint32_t)l4) * 4u;
        #pragma unroll
        for (int kc = 0; kc < 4; kc++) {
            uint32_t a = rb + (uint32_t)kc * 32u;     // +kc*8 words
            qa[mb][kc][0] = lds32(a);
            qa[mb][kc][1] = lds32(a + 8u * 36u * 4u);
            qa[mb][kc][2] = lds32(a + 16u);           // chpair +4
            qa[mb][kc][3] = lds32(a + 8u * 36u * 4u + 16u);
        }
    }

    float oc[2][8][4];
    float lsum[2][2] = {{0.f, 0.f}, {0.f, 0.f}};
    #pragma unroll
    for (int mb = 0; mb < 2; mb++)
        #pragma unroll
        for (int nc = 0; nc < 8; nc++)
            #pragma unroll
            for (int e = 0; e < 4; e++) oc[mb][nc][e] = 0.f;

    const uint32_t K2 = SB + K2OFF;
    const uint32_t V2 = SB + V2OFF;
    const uint32_t P2 = SB + P2OFF;

    #pragma unroll 1
    for (int kt = 0; kt < NTILES; kt++) {
        CP_WAIT1();                    // fp32 tile kt ready in stage (kt+1)&1
        __syncthreads();               // + everyone done with K2/V2 of tile kt-1

        const uint32_t fs = SB + (uint32_t)((kt + 1) & 1) * STAGEB;

        // ---- convert K: [chpair][key] fp16, pitch 72 ----
        {
            int kg = tid & 15;
            #pragma unroll
            for (int it = 0; it < 4; it++) {
                int cp = (tid >> 4) + it * 8;                    // 0..31
                float4 a = lds128f(fs + ((uint32_t)(2 * cp) * F32P + 4u * kg) * 4u);
                float4 c = lds128f(fs + ((uint32_t)(2 * cp + 1) * F32P + 4u * kg) * 4u);
                sts128(K2 + ((uint32_t)cp * 72u + 4u * kg) * 4u,
                       cvt2h(c.x, a.x), cvt2h(c.y, a.y), cvt2h(c.z, a.z), cvt2h(c.w, a.w));
            }
        }
        // ---- convert V: [keypair][ch] fp16, pitch 72 ----
        {
            int kvp = tid & 31;
            #pragma unroll
            for (int it = 0; it < 2; it++) {
                int cg = (tid >> 5) + it * 4;                    // 0..7
                uint32_t h[8];
                #pragma unroll
                for (int j = 0; j < 8; j++) {
                    float2 f = lds64f(fs + F32VO + ((uint32_t)(8 * cg + j) * F32P + 2u * kvp) * 4u);
                    h[j] = cvt2h(f.y, f.x);
                }
                uint32_t d = V2 + ((uint32_t)kvp * 72u + 8u * cg) * 4u;
                sts128(d,       h[0], h[1], h[2], h[3]);
                sts128(d + 16u, h[4], h[5], h[6], h[7]);
            }
        }
        __syncthreads();               // fp16 tiles visible; fp32 stage free

        // ---- issue cp.async for tile kt+2 into the just-freed stage ----
        {
            int nt = kt + 2;
            if (nt < NTILES) {
                const float* ks; const float* vs; int soff, str;
                if (nt < 16) { ks = ekp; vs = evp; soff = nt * NK;         str = SENC_; }
                else         { ks = kp;  vs = vp;  soff = nt * NK - SENC_; str = T_;    }
                int k4 = tid & 15;
                #pragma unroll
                for (int it = 0; it < 16; it++) {
                    int idx = tid + it * NT;
                    int m   = idx >> 10;
                    int ch  = (idx & 1023) >> 4;
                    const float* src = (m ? vs : ks) + (size_t)ch * str + soff + 4 * k4;
                    cp16(fs + (uint32_t)m * F32VO + ((uint32_t)ch * F32P + 4u * k4) * 4u, src);
                }
            }
            CP_COMMIT();
        }

        // ---- S = Q K^T (fp16 mma) ----
        float sc[2][8][4];
        #pragma unroll
        for (int mb = 0; mb < 2; mb++)
            #pragma unroll
            for (int nc = 0; nc < 8; nc++)
                #pragma unroll
                for (int e = 0; e < 4; e++) sc[mb][nc][e] = 0.f;

        #pragma unroll
        for (int kc = 0; kc < 4; kc++) {
            uint32_t rb = K2 + ((uint32_t)(kc * 8 + l4) * 72u + (uint32_t)lg) * 4u;
            #pragma unroll
            for (int nc = 0; nc < 8; nc++) {
                uint32_t a  = rb + (uint32_t)nc * 32u;       // key += 8
                uint32_t b0 = lds32(a);
                uint32_t b1 = lds32(a + 4u * 72u * 4u);      // chpair += 4
                mma16(sc[0][nc], qa[0][kc], b0, b1);
                mma16(sc[1][nc], qa[1][kc], b0, b1);
            }
        }

        // ---- softmax (log2 domain, max-free) -> P2 fp16 ----
        #pragma unroll
        for (int mb = 0; mb < 2; mb++) {
            uint32_t rb = P2 + ((uint32_t)(m0 + 16 * mb + lg) * 36u + (uint32_t)l4) * 4u;
            #pragma unroll
            for (int nc = 0; nc < 8; nc++) {
                float p0 = fexp2(sc[mb][nc][0]);
                float p1 = fexp2(sc[mb][nc][1]);
                float p2 = fexp2(sc[mb][nc][2]);
                float p3 = fexp2(sc[mb][nc][3]);
                lsum[mb][0] += p0 + p1;
                lsum[mb][1] += p2 + p3;
                sts32(rb + (uint32_t)nc * 16u,                 cvt2h(p1, p0));
                sts32(rb + (uint32_t)nc * 16u + 8u * 36u * 4u, cvt2h(p3, p2));
            }
        }
        __syncwarp();                  // P rows are warp-private

        // ---- O += P V^T ----
        #pragma unroll
        for (int kc = 0; kc < 4; kc++) {
            uint32_t pa[2][4];
            #pragma unroll
            for (int mb = 0; mb < 2; mb++) {
                uint32_t a = P2 + ((uint32_t)(m0 + 16 * mb + lg) * 36u + (uint32_t)(kc * 8 + l4)) * 4u;
                pa[mb][0] = lds32(a);
                pa[mb][1] = lds32(a + 8u * 36u * 4u);
                pa[mb][2] = lds32(a + 16u);
                pa[mb][3] = lds32(a + 8u * 36u * 4u + 16u);
            }
            uint32_t rb = V2 + ((uint32_t)(kc * 8 + l4) * 72u + (uint32_t)lg) * 4u;
            #pragma unroll
            for (int nc = 0; nc < 8; nc++) {
                uint32_t a  = rb + (uint32_t)nc * 32u;       // ch += 8
                uint32_t b0 = lds32(a);
                uint32_t b1 = lds32(a + 4u * 72u * 4u);      // keypair += 4
                mma16(oc[0][nc], pa[0], b0, b1);
                mma16(oc[1][nc], pa[1], b0, b1);
            }
        }
    }

    // ---- epilogue: quad-reduce row sums, normalize, sector-full scattered stores ----
    float inv[2][2];
    #pragma unroll
    for (int mb = 0; mb < 2; mb++)
        #pragma unroll
        for (int hh = 0; hh < 2; hh++) {
            float v = lsum[mb][hh];
            v += __shfl_xor_sync(0xffffffffu, v, 1);
            v += __shfl_xor_sync(0xffffffffu, v, 2);
            inv[mb][hh] = 1.0f / v;
        }

    #pragma unroll
    for (int mb = 0; mb < 2; mb++) {
        int q = q0 + m0 + 16 * mb + lg;
        #pragma unroll
        for (int nc = 0; nc < 8; nc++) {
            int ch = 8 * nc + 2 * l4;
            op[(size_t)ch       * T_ + q]     = oc[mb][nc][0] * inv[mb][0];
            op[(size_t)(ch + 1) * T_ + q]     = oc[mb][nc][1] * inv[mb][0];
            op[(size_t)ch       * T_ + q + 8] = oc[mb][nc][2] * inv[mb][1];
            op[(size_t)(ch + 1) * T_ + q + 8] = oc[mb][nc][3] * inv[mb][1];
        }
    }
}

extern "C" void kernel_launch(void* const* d_in, const int* in_sizes, int n_in,
                              void* d_out, int out_size)
{
    const float* x   = (const float*)d_in[0];   // (4, 1536, 1024)
    const float* ekv = (const float*)d_in[1];   // (4, 1024, 1024)
    float* out = (float*)d_out;                 // (4, 512, 1024)

    cudaFuncSetAttribute(attn_fp16_kernel, cudaFuncAttributeMaxDynamicSharedMemorySize, SMEM_BYTES);
    dim3 grid(T_ / MQ, B_ * H_);                // (8, 32) = 256 CTAs, 2/SM -> one wave
    attn_fp16_kernel<<<grid, NT, SMEM_BYTES>>>(x, ekv, out);
}